// round 2
// baseline (speedup 1.0000x reference)
#include <cuda_runtime.h>
#include <cuda_bf16.h>
#include <cstdint>

// Problem constants
#define BB 512
#define DD 128
#define CC 100000
#define TC 64                      // proxies per c-tile in the big kernel
#define NT ((CC + TC - 1) / TC)    // 1563 tiles
#define ATT_EPS 1e-5f

// Scratch (device globals; no allocations allowed)
__device__ float g_Xn[BB * DD];
__device__ float g_Pb[BB * DD];
__device__ float g_diag[BB];
__device__ float g_att[BB * BB];
__device__ float g_inv[BB];
__device__ float g_sx[BB];
__device__ float g_Dt[BB];
__device__ float g_Z[BB];
__device__ __nv_bfloat16 g_Xs16[BB * DD];

// ---------------------------------------------------------------------------
// helpers
// ---------------------------------------------------------------------------
__device__ __forceinline__ float bred128(float v, float* s4) {
    // block reduce over 128 threads; result broadcast to all threads
#pragma unroll
    for (int o = 16; o; o >>= 1) v += __shfl_xor_sync(0xffffffffu, v, o);
    __syncthreads();   // protect s4 from previous use
    if ((threadIdx.x & 31) == 0) s4[threadIdx.x >> 5] = v;
    __syncthreads();
    return s4[0] + s4[1] + s4[2] + s4[3];
}

__device__ __forceinline__ void mma_bf16(float* acc, uint32_t a0, uint32_t a1,
                                         uint32_t a2, uint32_t a3,
                                         uint32_t b0, uint32_t b1) {
    asm volatile(
        "mma.sync.aligned.m16n8k16.row.col.f32.bf16.bf16.f32 "
        "{%0,%1,%2,%3}, {%4,%5,%6,%7}, {%8,%9}, {%0,%1,%2,%3};\n"
        : "+f"(acc[0]), "+f"(acc[1]), "+f"(acc[2]), "+f"(acc[3])
        : "r"(a0), "r"(a1), "r"(a2), "r"(a3), "r"(b0), "r"(b1));
}

// Robust class-id fetch: the reference declares T as int64, but JAX with x64
// disabled materializes int32. Autodetect the layout (int64 little-endian with
// values < 2^31 has every odd int32 word == 0) and clamp for safety.
__device__ __forceinline__ int fetch_T(const int* T32, int b, int is64) {
    int t = is64 ? T32[2 * b] : T32[b];
    return min(max(t, 0), CC - 1);
}

__device__ __forceinline__ int detect_i64_block(const int* T32) {
    // all 128 threads scan; AND-reduce across block
    int ok = 1;
    for (int i = threadIdx.x; i < BB; i += DD)
        if (T32[2 * i + 1] != 0) ok = 0;
    return __syncthreads_and(ok);
}

// ---------------------------------------------------------------------------
// K1: Xn = l2norm(X); Pb = l2norm(proxies[T]); diag = <Pb,Xn>; Z = 0
// grid: BB blocks x DD threads
// ---------------------------------------------------------------------------
__global__ void k_prep(const float* __restrict__ X,
                       const int* __restrict__ T32,
                       const float* __restrict__ proxies) {
    __shared__ float s4[4];
    int b = blockIdx.x, d = threadIdx.x;
    int is64 = detect_i64_block(T32);

    float x = X[b * DD + d];
    float s = bred128(x * x, s4);
    float xn = x / fmaxf(sqrtf(s), 1e-12f);
    g_Xn[b * DD + d] = xn;

    int t = fetch_T(T32, b, is64);
    float p = proxies[(size_t)t * DD + d];
    float s2 = bred128(p * p, s4);
    float pb = p / fmaxf(sqrtf(s2), 1e-12f);
    g_Pb[b * DD + d] = pb;

    float dg = bred128(pb * xn, s4);
    if (d == 0) { g_diag[b] = dg; g_Z[b] = 0.f; }
}

// ---------------------------------------------------------------------------
// K2: att[b,j] = relu(0.5*(Pb[b].Xn[j] + diag[j])) + relu(Xn[b].Xn[j])
// grid: (16,16) blocks of 32x32 output tile, 256 threads, 2x2 per thread
// dynamic smem = (3*32*129 + 32)*4 = 49664 B
// ---------------------------------------------------------------------------
#define SMEM_ATT ((3 * 32 * 129 + 32) * 4)
__global__ void k_att() {
    extern __shared__ float smf[];
    float* PbS = smf;
    float* XnA = smf + 32 * 129;
    float* XnB = smf + 2 * 32 * 129;
    float* dgS = smf + 3 * 32 * 129;

    int tid = threadIdx.x;
    int b0 = blockIdx.y * 32, j0 = blockIdx.x * 32;
    for (int i = tid; i < 32 * DD; i += 256) {
        int r = i >> 7, d = i & 127;
        PbS[r * 129 + d] = g_Pb[(b0 + r) * DD + d];
        XnA[r * 129 + d] = g_Xn[(b0 + r) * DD + d];
        XnB[r * 129 + d] = g_Xn[(j0 + r) * DD + d];
    }
    if (tid < 32) dgS[tid] = g_diag[j0 + tid];
    __syncthreads();

    int tx = (tid & 15) * 2, ty = (tid >> 4) * 2;
    float apb00 = 0, apb01 = 0, apb10 = 0, apb11 = 0;
    float axx00 = 0, axx01 = 0, axx10 = 0, axx11 = 0;
#pragma unroll 4
    for (int d = 0; d < DD; d++) {
        float p0 = PbS[ty * 129 + d], p1 = PbS[(ty + 1) * 129 + d];
        float a0 = XnA[ty * 129 + d], a1 = XnA[(ty + 1) * 129 + d];
        float b0v = XnB[tx * 129 + d], b1v = XnB[(tx + 1) * 129 + d];
        apb00 += p0 * b0v; apb01 += p0 * b1v;
        apb10 += p1 * b0v; apb11 += p1 * b1v;
        axx00 += a0 * b0v; axx01 += a0 * b1v;
        axx10 += a1 * b0v; axx11 += a1 * b1v;
    }
    float dg0 = dgS[tx], dg1 = dgS[tx + 1];
    g_att[(b0 + ty) * BB + j0 + tx]         = fmaxf(0.5f * (apb00 + dg0), 0.f) + fmaxf(axx00, 0.f);
    g_att[(b0 + ty) * BB + j0 + tx + 1]     = fmaxf(0.5f * (apb01 + dg1), 0.f) + fmaxf(axx01, 0.f);
    g_att[(b0 + ty + 1) * BB + j0 + tx]     = fmaxf(0.5f * (apb10 + dg0), 0.f) + fmaxf(axx10, 0.f);
    g_att[(b0 + ty + 1) * BB + j0 + tx + 1] = fmaxf(0.5f * (apb11 + dg1), 0.f) + fmaxf(axx11, 0.f);
}

// ---------------------------------------------------------------------------
// K3: inv[k] = 1/(rowsum_k(att) + eps).  grid 64 x 256 (warp per row)
// ---------------------------------------------------------------------------
__global__ void k_rowsum() {
    int w = threadIdx.x >> 5, lane = threadIdx.x & 31;
    int k = blockIdx.x * 8 + w;
    float s = 0.f;
    for (int j = lane; j < BB; j += 32) s += g_att[k * BB + j];
#pragma unroll
    for (int o = 16; o; o >>= 1) s += __shfl_xor_sync(0xffffffffu, s, o);
    if (lane == 0) g_inv[k] = 1.f / (s + ATT_EPS);
}

// ---------------------------------------------------------------------------
// K4: W = (att * inv) @ Xn ; X2 = Xn + W ; Xs = 3*l2norm(X2)
//     store Xs (bf16), sx[b] = |Xs|^2, Dt[b] = relu(sx + 9 - 6*<Xs,Pb>)
// grid: BB blocks x DD threads
// ---------------------------------------------------------------------------
__global__ void k_xw() {
    __shared__ float ws[BB];
    __shared__ float s4[4];
    int b = blockIdx.x, d = threadIdx.x;
    for (int i = d; i < BB; i += DD) ws[i] = g_att[b * BB + i] * g_inv[i];
    __syncthreads();

    float a0 = 0, a1 = 0, a2 = 0, a3 = 0;
    for (int k = 0; k < BB; k += 4) {
        a0 += ws[k]     * g_Xn[(k)     * DD + d];
        a1 += ws[k + 1] * g_Xn[(k + 1) * DD + d];
        a2 += ws[k + 2] * g_Xn[(k + 2) * DD + d];
        a3 += ws[k + 3] * g_Xn[(k + 3) * DD + d];
    }
    float x2 = g_Xn[b * DD + d] + (a0 + a1) + (a2 + a3);
    float s = bred128(x2 * x2, s4);
    float xs = 3.f * x2 / fmaxf(sqrtf(s), 1e-12f);
    g_Xs16[b * DD + d] = __float2bfloat16(xs);
    float sxv = bred128(xs * xs, s4);
    float pb = g_Pb[b * DD + d];
    float dt = bred128(xs * pb, s4);
    if (d == 0) {
        g_sx[b] = sxv;
        g_Dt[b] = fmaxf(sxv + 9.f - 6.f * dt, 0.f);
    }
}

// ---------------------------------------------------------------------------
// K5 (big): Z[b] += sum_c exp(-relu(sx[b] + 9 - 2*<Xs[b], 3*l2norm(proxy_c)>))
// Persistent blocks; all 512 Xs rows in smem (bf16, row pad 136 = 68 u32,
// conflict-free frag loads); 64-proxy tiles double-buffered, normalized to
// bf16 on the fly; bf16 mma.sync m16n8k16; fused exp epilogue; per-thread
// running sums, one global atomicAdd flush at the end.
// 256 threads (8 warps), warp w owns rows [w*64, w*64+64).
// smem = (512*68 + 2*64*68)*4 = 174080 B
// ---------------------------------------------------------------------------
#define SMEM_BIG ((BB * 68 + 2 * TC * 68) * 4)

__global__ void __launch_bounds__(256) k_big(const float* __restrict__ proxies) {
    extern __shared__ uint32_t smu[];
    uint32_t* As = smu;                  // 512 x 68 u32 (bf16 pairs, pad 68)
    uint32_t* Ps = smu + BB * 68;        // 2 x 64 x 68

    const int tid = threadIdx.x;
    const int w = tid >> 5, lane = tid & 31, gid = lane >> 2, tig = lane & 3;

    // stage Xs(bf16) into padded smem
    const uint32_t* Xg = (const uint32_t*)g_Xs16;
    for (int i = tid; i < BB * (DD / 2); i += 256)
        As[(i >> 6) * 68 + (i & 63)] = Xg[i];

    float sx9[4][2];
#pragma unroll
    for (int m = 0; m < 4; m++) {
        int r = w * 64 + m * 16 + gid;
        sx9[m][0] = g_sx[r] + 9.f;
        sx9[m][1] = g_sx[r + 8] + 9.f;
    }
    float rs[4][2];
#pragma unroll
    for (int m = 0; m < 4; m++) { rs[m][0] = 0.f; rs[m][1] = 0.f; }

    // lambda: normalize a 64-row proxy tile (held in regs) into bf16 smem buf
    auto conv = [&](const float4* vv, uint32_t* dst) {
#pragma unroll
        for (int i = 0; i < 8; i++) {
            float4 q = vv[i];
            float s = q.x * q.x + q.y * q.y + q.z * q.z + q.w * q.w;
#pragma unroll
            for (int o = 16; o; o >>= 1) s += __shfl_xor_sync(0xffffffffu, s, o);
            float sc = (s > 0.f) ? 3.f * rsqrtf(s) : 0.f;
            __nv_bfloat162 h0 = __floats2bfloat162_rn(q.x * sc, q.y * sc);
            __nv_bfloat162 h1 = __floats2bfloat162_rn(q.z * sc, q.w * sc);
            uint32_t* p = dst + (w * 8 + i) * 68 + lane * 2;
            reinterpret_cast<__nv_bfloat162*>(p)[0] = h0;
            reinterpret_cast<__nv_bfloat162*>(p + 1)[0] = h1;
        }
    };

    const int stride = gridDim.x;
    int t = blockIdx.x;

    // prefetch + convert tile t into buffer 0
    float4 v[8];
#pragma unroll
    for (int i = 0; i < 8; i++) {
        int r = t * TC + w * 8 + i;
        v[i] = (r < CC) ? __ldg((const float4*)(proxies + (size_t)r * DD) + lane)
                        : make_float4(0.f, 0.f, 0.f, 0.f);
    }
    conv(v, Ps);
    __syncthreads();

    int buf = 0;
    while (t < NT) {
        int tn = t + stride;
        // issue next tile's global loads early (overlap with mma)
        float4 vn[8];
        if (tn < NT) {
#pragma unroll
            for (int i = 0; i < 8; i++) {
                int r = tn * TC + w * 8 + i;
                vn[i] = (r < CC) ? __ldg((const float4*)(proxies + (size_t)r * DD) + lane)
                                 : make_float4(0.f, 0.f, 0.f, 0.f);
            }
        }

        const uint32_t* Pb = Ps + buf * (TC * 68);
        float acc[4][8][4];
#pragma unroll
        for (int m = 0; m < 4; m++)
#pragma unroll
            for (int n = 0; n < 8; n++) {
                acc[m][n][0] = 0.f; acc[m][n][1] = 0.f;
                acc[m][n][2] = 0.f; acc[m][n][3] = 0.f;
            }

#pragma unroll
        for (int ks = 0; ks < 8; ks++) {
            int kb = ks * 8;   // u32 column base
            uint32_t a[4][4];
#pragma unroll
            for (int m = 0; m < 4; m++) {
                int base = (w * 64 + m * 16 + gid) * 68 + kb + tig;
                a[m][0] = As[base];
                a[m][1] = As[base + 8 * 68];
                a[m][2] = As[base + 4];
                a[m][3] = As[base + 8 * 68 + 4];
            }
            uint32_t bq[8][2];
#pragma unroll
            for (int n = 0; n < 8; n++) {
                int bb = (n * 8 + gid) * 68 + kb + tig;
                bq[n][0] = Pb[bb];
                bq[n][1] = Pb[bb + 4];
            }
#pragma unroll
            for (int m = 0; m < 4; m++)
#pragma unroll
                for (int n = 0; n < 8; n++)
                    mma_bf16(acc[m][n], a[m][0], a[m][1], a[m][2], a[m][3],
                             bq[n][0], bq[n][1]);
        }

        // fused epilogue: Dm -> exp(-Dm) -> per-row running sums
        int c0 = t * TC;
#pragma unroll
        for (int m = 0; m < 4; m++) {
#pragma unroll
            for (int n = 0; n < 8; n++) {
                int c = c0 + n * 8 + tig * 2;
                bool ok0 = c < CC, ok1 = (c + 1) < CC;
                float d00 = fmaxf(sx9[m][0] - 2.f * acc[m][n][0], 0.f);
                float d01 = fmaxf(sx9[m][0] - 2.f * acc[m][n][1], 0.f);
                float d10 = fmaxf(sx9[m][1] - 2.f * acc[m][n][2], 0.f);
                float d11 = fmaxf(sx9[m][1] - 2.f * acc[m][n][3], 0.f);
                rs[m][0] += (ok0 ? __expf(-d00) : 0.f) + (ok1 ? __expf(-d01) : 0.f);
                rs[m][1] += (ok0 ? __expf(-d10) : 0.f) + (ok1 ? __expf(-d11) : 0.f);
            }
        }

        if (tn < NT) conv(vn, Ps + (buf ^ 1) * (TC * 68));
        __syncthreads();
        buf ^= 1;
        t = tn;
    }

    // flush running sums: quad-reduce over tig, one atomicAdd per row
#pragma unroll
    for (int m = 0; m < 4; m++) {
#pragma unroll
        for (int h = 0; h < 2; h++) {
            float vsum = rs[m][h];
            vsum += __shfl_xor_sync(0xffffffffu, vsum, 1);
            vsum += __shfl_xor_sync(0xffffffffu, vsum, 2);
            if (tig == 0)
                atomicAdd(&g_Z[w * 64 + m * 16 + h * 8 + gid], vsum);
        }
    }
}

// ---------------------------------------------------------------------------
// K6: out = mean_b( Dt[b] + log(Z[b]) )
// ---------------------------------------------------------------------------
__global__ void k_final(float* __restrict__ out) {
    __shared__ float sw[16];
    int tid = threadIdx.x;
    float v = g_Dt[tid] + logf(g_Z[tid]);
#pragma unroll
    for (int o = 16; o; o >>= 1) v += __shfl_xor_sync(0xffffffffu, v, o);
    if ((tid & 31) == 0) sw[tid >> 5] = v;
    __syncthreads();
    if (tid < 32) {
        float u = (tid < 16) ? sw[tid] : 0.f;
#pragma unroll
        for (int o = 8; o; o >>= 1) u += __shfl_xor_sync(0xffffffffu, u, o);
        if (tid == 0) out[0] = u / (float)BB;
    }
}

// ---------------------------------------------------------------------------
// launch
// inputs (metadata order): X f32[512*128], indices int (unused),
//                          T int32-or-int64[512], proxies f32[100000*128]
// output: f32[1]
// ---------------------------------------------------------------------------
extern "C" void kernel_launch(void* const* d_in, const int* in_sizes, int n_in,
                              void* d_out, int out_size) {
    const float* X = (const float*)d_in[0];
    const int* T32 = (const int*)d_in[2];
    const float* proxies = (const float*)d_in[3];
    float* out = (float*)d_out;

    int sms = 0;
    cudaDeviceGetAttribute(&sms, cudaDevAttrMultiProcessorCount, 0);
    if (sms <= 0) sms = 148;
    cudaFuncSetAttribute(k_big, cudaFuncAttributeMaxDynamicSharedMemorySize, SMEM_BIG);
    cudaFuncSetAttribute(k_att, cudaFuncAttributeMaxDynamicSharedMemorySize, SMEM_ATT);

    k_prep<<<BB, DD>>>(X, T32, proxies);
    dim3 ga(16, 16);
    k_att<<<ga, 256, SMEM_ATT>>>();
    k_rowsum<<<64, 256>>>();
    k_xw<<<BB, DD>>>();
    k_big<<<sms, 256, SMEM_BIG>>>(proxies);
    k_final<<<1, BB>>>(out);
}

// round 3
// speedup vs baseline: 1.5214x; 1.5214x over previous
#include <cuda_runtime.h>
#include <cuda_bf16.h>
#include <cstdint>

// Problem constants
#define BB 512
#define DD 128
#define CC 100000
#define TC 64                      // proxies per c-tile in the big kernel
#define NT ((CC + TC - 1) / TC)    // 1563 tiles
#define ATT_EPS 1e-5f

// Scratch (device globals; no allocations allowed)
__device__ float g_Xn[BB * DD];
__device__ float g_Pb[BB * DD];
__device__ float g_diag[BB];
__device__ float g_att[BB * BB];
__device__ float g_inv[BB];
__device__ float g_sx[BB];
__device__ float g_Dt[BB];
__device__ float g_Z[BB];
__device__ __nv_bfloat16 g_Xs16[BB * DD];

// ---------------------------------------------------------------------------
// helpers
// ---------------------------------------------------------------------------
__device__ __forceinline__ uint32_t s2u(const void* p) {
    uint32_t a;
    asm("{ .reg .u64 t; cvta.to.shared.u64 t, %1; cvt.u32.u64 %0, t; }"
        : "=r"(a) : "l"(p));
    return a;
}

__device__ __forceinline__ float bred128(float v, float* s4) {
#pragma unroll
    for (int o = 16; o; o >>= 1) v += __shfl_xor_sync(0xffffffffu, v, o);
    __syncthreads();
    if ((threadIdx.x & 31) == 0) s4[threadIdx.x >> 5] = v;
    __syncthreads();
    return s4[0] + s4[1] + s4[2] + s4[3];
}

__device__ __forceinline__ float bred256(float v, float* s8) {
#pragma unroll
    for (int o = 16; o; o >>= 1) v += __shfl_xor_sync(0xffffffffu, v, o);
    __syncthreads();
    if ((threadIdx.x & 31) == 0) s8[threadIdx.x >> 5] = v;
    __syncthreads();
    float r = 0.f;
#pragma unroll
    for (int j = 0; j < 8; j++) r += s8[j];
    return r;
}

__device__ __forceinline__ void mma_bf16(float* acc, uint32_t a0, uint32_t a1,
                                         uint32_t a2, uint32_t a3,
                                         uint32_t b0, uint32_t b1) {
    asm volatile(
        "mma.sync.aligned.m16n8k16.row.col.f32.bf16.bf16.f32 "
        "{%0,%1,%2,%3}, {%4,%5,%6,%7}, {%8,%9}, {%0,%1,%2,%3};\n"
        : "+f"(acc[0]), "+f"(acc[1]), "+f"(acc[2]), "+f"(acc[3])
        : "r"(a0), "r"(a1), "r"(a2), "r"(a3), "r"(b0), "r"(b1));
}

__device__ __forceinline__ void ldsm4(uint32_t addr, uint32_t* r) {
    asm volatile("ldmatrix.sync.aligned.m8n8.x4.shared.b16 {%0,%1,%2,%3}, [%4];"
                 : "=r"(r[0]), "=r"(r[1]), "=r"(r[2]), "=r"(r[3]) : "r"(addr));
}

// Robust class-id fetch (JAX x64-disabled materializes int32 for declared int64)
__device__ __forceinline__ int fetch_T(const int* T32, int b, int is64) {
    int t = is64 ? T32[2 * b] : T32[b];
    return min(max(t, 0), CC - 1);
}
__device__ __forceinline__ int detect_i64_block(const int* T32) {
    int ok = 1;
    for (int i = threadIdx.x; i < BB; i += blockDim.x)
        if (T32[2 * i + 1] != 0) ok = 0;
    return __syncthreads_and(ok);
}

// ---------------------------------------------------------------------------
// K1: Xn = l2norm(X); Pb = l2norm(proxies[T]); diag = <Pb,Xn>; Z = 0
// ---------------------------------------------------------------------------
__global__ void k_prep(const float* __restrict__ X,
                       const int* __restrict__ T32,
                       const float* __restrict__ proxies) {
    __shared__ float s4[4];
    int b = blockIdx.x, d = threadIdx.x;
    int is64 = detect_i64_block(T32);

    float x = X[b * DD + d];
    float s = bred128(x * x, s4);
    float xn = x / fmaxf(sqrtf(s), 1e-12f);
    g_Xn[b * DD + d] = xn;

    int t = fetch_T(T32, b, is64);
    float p = proxies[(size_t)t * DD + d];
    float s2 = bred128(p * p, s4);
    float pb = p / fmaxf(sqrtf(s2), 1e-12f);
    g_Pb[b * DD + d] = pb;

    float dg = bred128(pb * xn, s4);
    if (d == 0) { g_diag[b] = dg; g_Z[b] = 0.f; }
}

// ---------------------------------------------------------------------------
// K2: att[b,j] = relu(0.5*(Pb[b].Xn[j] + diag[j])) + relu(Xn[b].Xn[j])
// ---------------------------------------------------------------------------
#define SMEM_ATT ((3 * 32 * 129 + 32) * 4)
__global__ void k_att() {
    extern __shared__ float smf[];
    float* PbS = smf;
    float* XnA = smf + 32 * 129;
    float* XnB = smf + 2 * 32 * 129;
    float* dgS = smf + 3 * 32 * 129;

    int tid = threadIdx.x;
    int b0 = blockIdx.y * 32, j0 = blockIdx.x * 32;
    for (int i = tid; i < 32 * DD; i += 256) {
        int r = i >> 7, d = i & 127;
        PbS[r * 129 + d] = g_Pb[(b0 + r) * DD + d];
        XnA[r * 129 + d] = g_Xn[(b0 + r) * DD + d];
        XnB[r * 129 + d] = g_Xn[(j0 + r) * DD + d];
    }
    if (tid < 32) dgS[tid] = g_diag[j0 + tid];
    __syncthreads();

    int tx = (tid & 15) * 2, ty = (tid >> 4) * 2;
    float apb00 = 0, apb01 = 0, apb10 = 0, apb11 = 0;
    float axx00 = 0, axx01 = 0, axx10 = 0, axx11 = 0;
#pragma unroll 4
    for (int d = 0; d < DD; d++) {
        float p0 = PbS[ty * 129 + d], p1 = PbS[(ty + 1) * 129 + d];
        float a0 = XnA[ty * 129 + d], a1 = XnA[(ty + 1) * 129 + d];
        float b0v = XnB[tx * 129 + d], b1v = XnB[(tx + 1) * 129 + d];
        apb00 += p0 * b0v; apb01 += p0 * b1v;
        apb10 += p1 * b0v; apb11 += p1 * b1v;
        axx00 += a0 * b0v; axx01 += a0 * b1v;
        axx10 += a1 * b0v; axx11 += a1 * b1v;
    }
    float dg0 = dgS[tx], dg1 = dgS[tx + 1];
    g_att[(b0 + ty) * BB + j0 + tx]         = fmaxf(0.5f * (apb00 + dg0), 0.f) + fmaxf(axx00, 0.f);
    g_att[(b0 + ty) * BB + j0 + tx + 1]     = fmaxf(0.5f * (apb01 + dg1), 0.f) + fmaxf(axx01, 0.f);
    g_att[(b0 + ty + 1) * BB + j0 + tx]     = fmaxf(0.5f * (apb10 + dg0), 0.f) + fmaxf(axx10, 0.f);
    g_att[(b0 + ty + 1) * BB + j0 + tx + 1] = fmaxf(0.5f * (apb11 + dg1), 0.f) + fmaxf(axx11, 0.f);
}

// ---------------------------------------------------------------------------
// K3: inv[k] = 1/(rowsum_k(att) + eps)
// ---------------------------------------------------------------------------
__global__ void k_rowsum() {
    int w = threadIdx.x >> 5, lane = threadIdx.x & 31;
    int k = blockIdx.x * 8 + w;
    float s = 0.f;
    for (int j = lane; j < BB; j += 32) s += g_att[k * BB + j];
#pragma unroll
    for (int o = 16; o; o >>= 1) s += __shfl_xor_sync(0xffffffffu, s, o);
    if (lane == 0) g_inv[k] = 1.f / (s + ATT_EPS);
}

// ---------------------------------------------------------------------------
// K4: W = (att * inv) @ Xn ; X2 = Xn + W ; Xs = 3*l2norm(X2)
// 512 blocks x 256 threads: 8-way k-split x float4 over d, two-phase reduce.
// ---------------------------------------------------------------------------
__global__ void __launch_bounds__(256) k_xw() {
    __shared__ float ws[BB];
    __shared__ float4 part[8][32];
    __shared__ float s8[8];
    int b = blockIdx.x, tid = threadIdx.x;
    int kp = tid >> 5, d4 = tid & 31;

    for (int i = tid; i < BB; i += 256) ws[i] = g_att[b * BB + i] * g_inv[i];
    __syncthreads();

    const float4* Xn4 = (const float4*)g_Xn;
    float4 acc = make_float4(0.f, 0.f, 0.f, 0.f);
    int k0 = kp * 64;
#pragma unroll 8
    for (int kk = 0; kk < 64; kk++) {
        int k = k0 + kk;
        float wv = ws[k];
        float4 x = Xn4[k * 32 + d4];
        acc.x += wv * x.x; acc.y += wv * x.y;
        acc.z += wv * x.z; acc.w += wv * x.w;
    }
    part[kp][d4] = acc;
    __syncthreads();

    int d = tid;
    float x2 = 0.f;
    if (tid < DD) {
        float s = 0.f;
        const float* pf = (const float*)part;
#pragma unroll
        for (int j = 0; j < 8; j++) s += pf[j * 128 + d];
        x2 = g_Xn[b * DD + d] + s;
    }
    float s = bred256(x2 * x2, s8);
    float xs = 3.f * x2 / fmaxf(sqrtf(s), 1e-12f);
    if (tid < DD) g_Xs16[b * DD + d] = __float2bfloat16(xs);
    float sxv = bred256(xs * xs, s8);
    float pb = (tid < DD) ? g_Pb[b * DD + d] : 0.f;
    float dt = bred256(xs * pb, s8);
    if (tid == 0) {
        g_sx[b] = sxv;
        g_Dt[b] = fmaxf(sxv + 9.f - 6.f * dt, 0.f);
    }
}

// ---------------------------------------------------------------------------
// K5 (big): Z[b] += sum_c exp(-relu(sx[b] + 9 - 2*<Xs[b], 3*l2norm(proxy_c)>))
// 512 threads (16 warps), warp w owns rows [w*32, w*32+32) (2 m-frags).
// cp.async staging (f32) -> on-the-fly normalize to bf16 Ps -> ldmatrix.x4
// fragment loads -> mma.sync bf16 -> fused exp epilogue.
// smem: As 512x68 u32 | Ps 64x68 u32 | staging 64x128 f32 = 189440 B
// ---------------------------------------------------------------------------
#define SMEM_BIG ((BB * 68 + TC * 68) * 4 + TC * DD * 4)

__device__ __forceinline__ void cp_tile(const float* __restrict__ proxies,
                                        uint32_t s_st, int t, int tid) {
    if (t >= 0) {
#pragma unroll
        for (int j = 0; j < 4; j++) {
            int idx = tid + j * 512;          // 0..2047
            int row = idx >> 5, c4 = idx & 31;
            int gr = t * TC + row;
            int valid = gr < CC;
            const float4* g = (const float4*)(proxies + (size_t)(valid ? gr : 0) * DD) + c4;
            uint32_t dst = s_st + idx * 16;
            int sz = valid ? 16 : 0;          // sz=0 -> zero-fill, no read
            asm volatile("cp.async.cg.shared.global [%0], [%1], 16, %2;"
                         :: "r"(dst), "l"(g), "r"(sz));
        }
    }
    asm volatile("cp.async.commit_group;");
}

__global__ void __launch_bounds__(512, 1) k_big(const float* __restrict__ proxies) {
    extern __shared__ uint32_t smu[];
    uint32_t* As = smu;                        // 512 x 68
    uint32_t* Ps = smu + BB * 68;              // 64 x 68
    float* Stg = (float*)(smu + (BB + TC) * 68);  // 64 x 128 f32

    const int tid = threadIdx.x;
    const int w = tid >> 5, lane = tid & 31, gid = lane >> 2, tig = lane & 3;
    const int grp = lane >> 3, lr = lane & 7;
    const uint32_t s_as = s2u(As), s_ps = s2u(Ps), s_st = s2u(Stg);

    const int stride = gridDim.x;
    int t = blockIdx.x;

    // issue cp.async for first tile, then stage Xs while it flies
    cp_tile(proxies, s_st, t, tid);

    const uint32_t* Xg = (const uint32_t*)g_Xs16;
    for (int i = tid; i < BB * (DD / 2); i += 512)
        As[(i >> 6) * 68 + (i & 63)] = Xg[i];

    float sx9[2][2], rs[2][2];
#pragma unroll
    for (int mf = 0; mf < 2; mf++) {
        int r = w * 32 + mf * 16 + gid;
        sx9[mf][0] = g_sx[r] + 9.f;
        sx9[mf][1] = g_sx[r + 8] + 9.f;
        rs[mf][0] = 0.f; rs[mf][1] = 0.f;
    }

    // precompute lane-invariant ldmatrix address pieces
    // A: row = w*32 + mf*16 + (grp&1)*8 + lr ; u32 col = kb + (grp>>1)*4
    // B: row = np*16 + (grp>>1)*8 + lr      ; u32 col = kb + (grp&1)*4
    const uint32_t aRowBase = (uint32_t)(w * 32 + (grp & 1) * 8 + lr);
    const uint32_t aKadd = (uint32_t)((grp >> 1) * 4);
    const uint32_t bRowBase = (uint32_t)((grp >> 1) * 8 + lr);
    const uint32_t bKadd = (uint32_t)((grp & 1) * 4);

    asm volatile("cp.async.wait_group 0;");
    __syncthreads();

    while (t < NT) {
        // normalize staging tile -> bf16 Ps (warp w handles rows w*4..w*4+3)
#pragma unroll
        for (int i = 0; i < 4; i++) {
            int row = w * 4 + i;
            float4 q = ((const float4*)Stg)[row * 32 + lane];
            float s = q.x * q.x + q.y * q.y + q.z * q.z + q.w * q.w;
#pragma unroll
            for (int o = 16; o; o >>= 1) s += __shfl_xor_sync(0xffffffffu, s, o);
            float sc = (s > 0.f) ? 3.f * rsqrtf(s) : 0.f;
            __nv_bfloat162 h0 = __floats2bfloat162_rn(q.x * sc, q.y * sc);
            __nv_bfloat162 h1 = __floats2bfloat162_rn(q.z * sc, q.w * sc);
            uint32_t* p = Ps + row * 68 + lane * 2;
            reinterpret_cast<__nv_bfloat162*>(p)[0] = h0;
            reinterpret_cast<__nv_bfloat162*>(p + 1)[0] = h1;
        }
        __syncthreads();   // Ps ready; staging fully consumed

        int tn = t + stride;
        cp_tile(proxies, s_st, (tn < NT) ? tn : -1, tid);  // overlaps with mma

        float acc[2][8][4];
#pragma unroll
        for (int mf = 0; mf < 2; mf++)
#pragma unroll
            for (int n = 0; n < 8; n++) {
                acc[mf][n][0] = 0.f; acc[mf][n][1] = 0.f;
                acc[mf][n][2] = 0.f; acc[mf][n][3] = 0.f;
            }

#pragma unroll
        for (int ks = 0; ks < 8; ks++) {
            uint32_t kb = ks * 8;
            uint32_t a[2][4];
#pragma unroll
            for (int mf = 0; mf < 2; mf++)
                ldsm4(s_as + ((aRowBase + mf * 16) * 68 + kb + aKadd) * 4, a[mf]);
            uint32_t bq[8][2];
#pragma unroll
            for (int np = 0; np < 4; np++) {
                uint32_t r4[4];
                ldsm4(s_ps + ((bRowBase + np * 16) * 68 + kb + bKadd) * 4, r4);
                bq[2 * np][0] = r4[0]; bq[2 * np][1] = r4[1];
                bq[2 * np + 1][0] = r4[2]; bq[2 * np + 1][1] = r4[3];
            }
#pragma unroll
            for (int mf = 0; mf < 2; mf++)
#pragma unroll
                for (int n = 0; n < 8; n++)
                    mma_bf16(acc[mf][n], a[mf][0], a[mf][1], a[mf][2], a[mf][3],
                             bq[n][0], bq[n][1]);
        }

        // fused epilogue (pad rows contribute exp(-18) ~ 1.5e-8: negligible)
#pragma unroll
        for (int mf = 0; mf < 2; mf++) {
#pragma unroll
            for (int n = 0; n < 8; n++) {
                float d00 = fmaxf(fmaf(-2.f, acc[mf][n][0], sx9[mf][0]), 0.f);
                float d01 = fmaxf(fmaf(-2.f, acc[mf][n][1], sx9[mf][0]), 0.f);
                float d10 = fmaxf(fmaf(-2.f, acc[mf][n][2], sx9[mf][1]), 0.f);
                float d11 = fmaxf(fmaf(-2.f, acc[mf][n][3], sx9[mf][1]), 0.f);
                rs[mf][0] += __expf(-d00) + __expf(-d01);
                rs[mf][1] += __expf(-d10) + __expf(-d11);
            }
        }

        asm volatile("cp.async.wait_group 0;");
        __syncthreads();   // staging(tn) ready; Ps reusable
        t = tn;
    }

    // flush: quad-reduce over tig, one atomicAdd per row
#pragma unroll
    for (int mf = 0; mf < 2; mf++) {
#pragma unroll
        for (int h = 0; h < 2; h++) {
            float v = rs[mf][h];
            v += __shfl_xor_sync(0xffffffffu, v, 1);
            v += __shfl_xor_sync(0xffffffffu, v, 2);
            if (tig == 0)
                atomicAdd(&g_Z[w * 32 + mf * 16 + h * 8 + gid], v);
        }
    }
}

// ---------------------------------------------------------------------------
// K6: out = mean_b( Dt[b] + log(Z[b]) )
// ---------------------------------------------------------------------------
__global__ void k_final(float* __restrict__ out) {
    __shared__ float sw[16];
    int tid = threadIdx.x;
    float v = g_Dt[tid] + logf(g_Z[tid]);
#pragma unroll
    for (int o = 16; o; o >>= 1) v += __shfl_xor_sync(0xffffffffu, v, o);
    if ((tid & 31) == 0) sw[tid >> 5] = v;
    __syncthreads();
    if (tid < 32) {
        float u = (tid < 16) ? sw[tid] : 0.f;
#pragma unroll
        for (int o = 8; o; o >>= 1) u += __shfl_xor_sync(0xffffffffu, u, o);
        if (tid == 0) out[0] = u / (float)BB;
    }
}

// ---------------------------------------------------------------------------
// launch
// ---------------------------------------------------------------------------
extern "C" void kernel_launch(void* const* d_in, const int* in_sizes, int n_in,
                              void* d_out, int out_size) {
    const float* X = (const float*)d_in[0];
    const int* T32 = (const int*)d_in[2];
    const float* proxies = (const float*)d_in[3];
    float* out = (float*)d_out;

    int sms = 0;
    cudaDeviceGetAttribute(&sms, cudaDevAttrMultiProcessorCount, 0);
    if (sms <= 0) sms = 148;
    cudaFuncSetAttribute(k_big, cudaFuncAttributeMaxDynamicSharedMemorySize, SMEM_BIG);
    cudaFuncSetAttribute(k_att, cudaFuncAttributeMaxDynamicSharedMemorySize, SMEM_ATT);

    k_prep<<<BB, DD>>>(X, T32, proxies);
    dim3 ga(16, 16);
    k_att<<<ga, 256, SMEM_ATT>>>();
    k_rowsum<<<64, 256>>>();
    k_xw<<<BB, 256>>>();
    k_big<<<sms, 512, SMEM_BIG>>>(proxies);
    k_final<<<1, BB>>>(out);
}

// round 5
// speedup vs baseline: 1.6612x; 1.0919x over previous
#include <cuda_runtime.h>
#include <cuda_bf16.h>
#include <cstdint>

// Problem constants
#define BB 512
#define DD 128
#define CC 100000
#define TC 64                      // proxies per c-tile in the big kernel
#define NT ((CC + TC - 1) / TC)    // 1563 tiles
#define ATT_EPS 1e-5f

// Scratch (device globals; no allocations allowed)
__device__ float g_Xn[BB * DD];
__device__ float g_Pb[BB * DD];
__device__ float g_diag[BB];
__device__ float g_att[BB * BB];
__device__ float g_rowsum[BB];     // rowsum[k] = sum_j att[k, j]
__device__ float g_Dt[BB];
__device__ float g_Z[BB];
__device__ __nv_bfloat16 g_Xs16[BB * DD];

// ---------------------------------------------------------------------------
// helpers
// ---------------------------------------------------------------------------
__device__ __forceinline__ uint32_t s2u(const void* p) {
    uint32_t a;
    asm("{ .reg .u64 t; cvta.to.shared.u64 t, %1; cvt.u32.u64 %0, t; }"
        : "=r"(a) : "l"(p));
    return a;
}

__device__ __forceinline__ float bred128(float v, float* s4) {
#pragma unroll
    for (int o = 16; o; o >>= 1) v += __shfl_xor_sync(0xffffffffu, v, o);
    __syncthreads();
    if ((threadIdx.x & 31) == 0) s4[threadIdx.x >> 5] = v;
    __syncthreads();
    return s4[0] + s4[1] + s4[2] + s4[3];
}

__device__ __forceinline__ void mma_bf16(float* acc, uint32_t a0, uint32_t a1,
                                         uint32_t a2, uint32_t a3,
                                         uint32_t b0, uint32_t b1) {
    asm volatile(
        "mma.sync.aligned.m16n8k16.row.col.f32.bf16.bf16.f32 "
        "{%0,%1,%2,%3}, {%4,%5,%6,%7}, {%8,%9}, {%0,%1,%2,%3};\n"
        : "+f"(acc[0]), "+f"(acc[1]), "+f"(acc[2]), "+f"(acc[3])
        : "r"(a0), "r"(a1), "r"(a2), "r"(a3), "r"(b0), "r"(b1));
}

__device__ __forceinline__ void ldsm4(uint32_t addr, uint32_t* r) {
    asm volatile("ldmatrix.sync.aligned.m8n8.x4.shared.b16 {%0,%1,%2,%3}, [%4];"
                 : "=r"(r[0]), "=r"(r[1]), "=r"(r[2]), "=r"(r[3]) : "r"(addr));
}

__device__ __forceinline__ float ex2f(float x) {
    float r;
    asm("ex2.approx.ftz.f32 %0, %1;" : "=f"(r) : "f"(x));
    return r;
}

__device__ __forceinline__ uint32_t f2b2(float a, float b) {
    __nv_bfloat162 h = __floats2bfloat162_rn(a, b);
    return *(uint32_t*)&h;
}

// Robust class-id fetch (JAX x64-disabled materializes int32 for declared int64)
__device__ __forceinline__ int fetch_T(const int* T32, int b, int is64) {
    int t = is64 ? T32[2 * b] : T32[b];
    return min(max(t, 0), CC - 1);
}
__device__ __forceinline__ int detect_i64_block(const int* T32) {
    int ok = 1;
    for (int i = threadIdx.x; i < BB; i += blockDim.x)
        if (T32[2 * i + 1] != 0) ok = 0;
    return __syncthreads_and(ok);
}

// ---------------------------------------------------------------------------
// K1: Xn = l2norm(X); Pb = l2norm(proxies[T]); diag = <Pb,Xn>; zero Z/rowsum
// ---------------------------------------------------------------------------
__global__ void k_prep(const float* __restrict__ X,
                       const int* __restrict__ T32,
                       const float* __restrict__ proxies) {
    __shared__ float s4[4];
    int b = blockIdx.x, d = threadIdx.x;
    int is64 = detect_i64_block(T32);

    float x = X[b * DD + d];
    float s = bred128(x * x, s4);
    float xn = x / fmaxf(sqrtf(s), 1e-12f);
    g_Xn[b * DD + d] = xn;

    int t = fetch_T(T32, b, is64);
    float p = proxies[(size_t)t * DD + d];
    float s2 = bred128(p * p, s4);
    float pb = p / fmaxf(sqrtf(s2), 1e-12f);
    g_Pb[b * DD + d] = pb;

    float dg = bred128(pb * xn, s4);
    if (d == 0) g_diag[b] = dg;
    if (b < 4) { g_rowsum[b * DD + d] = 0.f; }
    if (d == 0) g_Z[b] = 0.f;
}

// ---------------------------------------------------------------------------
// K2: att[b,j] = relu(0.5*(Pb[b].Xn[j] + diag[j])) + relu(Xn[b].Xn[j])
//     + atomic accumulation of ROW sums (sum over j at fixed b)
// ---------------------------------------------------------------------------
#define SMEM_ATT ((3 * 32 * 129 + 32 + 32) * 4)
__global__ void k_att() {
    extern __shared__ float smf[];
    float* PbS = smf;
    float* XnA = smf + 32 * 129;
    float* XnB = smf + 2 * 32 * 129;
    float* dgS = smf + 3 * 32 * 129;
    float* rsum = smf + 3 * 32 * 129 + 32;

    int tid = threadIdx.x;
    int b0 = blockIdx.y * 32, j0 = blockIdx.x * 32;
    for (int i = tid; i < 32 * DD; i += 256) {
        int r = i >> 7, d = i & 127;
        PbS[r * 129 + d] = g_Pb[(b0 + r) * DD + d];
        XnA[r * 129 + d] = g_Xn[(b0 + r) * DD + d];
        XnB[r * 129 + d] = g_Xn[(j0 + r) * DD + d];
    }
    if (tid < 32) { dgS[tid] = g_diag[j0 + tid]; rsum[tid] = 0.f; }
    __syncthreads();

    int tx = (tid & 15) * 2, ty = (tid >> 4) * 2;
    float apb00 = 0, apb01 = 0, apb10 = 0, apb11 = 0;
    float axx00 = 0, axx01 = 0, axx10 = 0, axx11 = 0;
#pragma unroll 4
    for (int d = 0; d < DD; d++) {
        float p0 = PbS[ty * 129 + d], p1 = PbS[(ty + 1) * 129 + d];
        float a0 = XnA[ty * 129 + d], a1 = XnA[(ty + 1) * 129 + d];
        float b0v = XnB[tx * 129 + d], b1v = XnB[(tx + 1) * 129 + d];
        apb00 += p0 * b0v; apb01 += p0 * b1v;
        apb10 += p1 * b0v; apb11 += p1 * b1v;
        axx00 += a0 * b0v; axx01 += a0 * b1v;
        axx10 += a1 * b0v; axx11 += a1 * b1v;
    }
    float dg0 = dgS[tx], dg1 = dgS[tx + 1];
    float a00 = fmaxf(0.5f * (apb00 + dg0), 0.f) + fmaxf(axx00, 0.f);
    float a01 = fmaxf(0.5f * (apb01 + dg1), 0.f) + fmaxf(axx01, 0.f);
    float a10 = fmaxf(0.5f * (apb10 + dg0), 0.f) + fmaxf(axx10, 0.f);
    float a11 = fmaxf(0.5f * (apb11 + dg1), 0.f) + fmaxf(axx11, 0.f);
    g_att[(b0 + ty) * BB + j0 + tx]         = a00;
    g_att[(b0 + ty) * BB + j0 + tx + 1]     = a01;
    g_att[(b0 + ty + 1) * BB + j0 + tx]     = a10;
    g_att[(b0 + ty + 1) * BB + j0 + tx + 1] = a11;

    // ROW sums: sum over columns j at fixed row b (reference divides [b,k] by
    // rowsum of row k, so the denominator table is indexed by row id)
    atomicAdd(&rsum[ty], a00 + a01);
    atomicAdd(&rsum[ty + 1], a10 + a11);
    __syncthreads();
    if (tid < 32) atomicAdd(&g_rowsum[b0 + tid], rsum[tid]);
}

// ---------------------------------------------------------------------------
// K3: for 4 rows b per block: W[b,:] = sum_k att[b,k]/(rowsum[k]+eps) * Xn[k,:]
//     X2 = Xn + W; Xs = 3*l2norm(X2) -> bf16 ; Dt = relu(18 - 6*<Xs,Pb>)
// 128 blocks x 256 threads
// ---------------------------------------------------------------------------
__global__ void __launch_bounds__(256) k_xw() {
    __shared__ float ws[4][BB];
    __shared__ float4 part[8][4][32];
    __shared__ float wsA[8], wsB[8];
    int tid = threadIdx.x;
    int b0 = blockIdx.x * 4;
    int kp = tid >> 5, d4 = tid & 31;

    for (int i = tid; i < BB; i += 256) {
        float inv = 1.f / (g_rowsum[i] + ATT_EPS);
        ws[0][i] = g_att[(b0 + 0) * BB + i] * inv;
        ws[1][i] = g_att[(b0 + 1) * BB + i] * inv;
        ws[2][i] = g_att[(b0 + 2) * BB + i] * inv;
        ws[3][i] = g_att[(b0 + 3) * BB + i] * inv;
    }
    __syncthreads();

    const float4* Xn4 = (const float4*)g_Xn;
    float4 acc[4];
#pragma unroll
    for (int r = 0; r < 4; r++) acc[r] = make_float4(0.f, 0.f, 0.f, 0.f);
    int k0 = kp * 64;
#pragma unroll 4
    for (int kk = 0; kk < 64; kk++) {
        int k = k0 + kk;
        float4 x = Xn4[k * 32 + d4];
#pragma unroll
        for (int r = 0; r < 4; r++) {
            float wv = ws[r][k];
            acc[r].x += wv * x.x; acc[r].y += wv * x.y;
            acc[r].z += wv * x.z; acc[r].w += wv * x.w;
        }
    }
#pragma unroll
    for (int r = 0; r < 4; r++) part[kp][r][d4] = acc[r];
    __syncthreads();

    // final: row = tid>>6 (0..3), j = tid&63 handles d=j and d=j+64
    int row = tid >> 6, j = tid & 63;
    float s1 = 0.f, s2 = 0.f;
#pragma unroll
    for (int p = 0; p < 8; p++) {
        const float* pf = (const float*)part[p][row];
        s1 += pf[j];
        s2 += pf[j + 64];
    }
    float x2a = g_Xn[(b0 + row) * DD + j] + s1;
    float x2b = g_Xn[(b0 + row) * DD + j + 64] + s2;

    float ssq = x2a * x2a + x2b * x2b;
#pragma unroll
    for (int o = 16; o; o >>= 1) ssq += __shfl_xor_sync(0xffffffffu, ssq, o);
    if ((tid & 31) == 0) wsA[tid >> 5] = ssq;
    __syncthreads();
    float stot = wsA[row * 2] + wsA[row * 2 + 1];
    float sc = 3.f / fmaxf(sqrtf(stot), 1e-12f);
    float xsa = x2a * sc, xsb = x2b * sc;
    g_Xs16[(b0 + row) * DD + j] = __float2bfloat16(xsa);
    g_Xs16[(b0 + row) * DD + j + 64] = __float2bfloat16(xsb);

    float dp = xsa * g_Pb[(b0 + row) * DD + j] + xsb * g_Pb[(b0 + row) * DD + j + 64];
#pragma unroll
    for (int o = 16; o; o >>= 1) dp += __shfl_xor_sync(0xffffffffu, dp, o);
    if ((tid & 31) == 0) wsB[tid >> 5] = dp;
    __syncthreads();
    if (j == 0) {
        float dt = wsB[row * 2] + wsB[row * 2 + 1];
        g_Dt[b0 + row] = fmaxf(18.f - 6.f * dt, 0.f);
    }
}

// ---------------------------------------------------------------------------
// K4 (big): Z[b] += sum_c exp(-relu(18 - 2*<Xs[b], 3*l2norm(proxy_c)>))
// 512 threads (16 warps), warp w owns rows [w*32, w*32+32).
// 2-stage cp.async f32 staging -> 8-thread/row normalize to bf16 Ps ->
// ldmatrix.x4 -> mma.sync bf16 -> folded ex2 epilogue.
// smem: As 512x68 | Ps 64x68 | 2 x staging 64x128 f32 = 222208 B
// ---------------------------------------------------------------------------
#define STGF (TC * DD)                 // floats per staging buffer
#define SMEM_BIG (((BB + TC) * 68) * 4 + 2 * STGF * 4)

__device__ __forceinline__ void cp_tile(const float* __restrict__ proxies,
                                        uint32_t s_st, int t, int tid) {
    if (t >= 0) {
#pragma unroll
        for (int j = 0; j < 4; j++) {
            int idx = tid + j * 512;          // 0..2047
            int row = idx >> 5, c4 = idx & 31;
            int gr = t * TC + row;
            int valid = gr < CC;
            const float4* g = (const float4*)(proxies + (size_t)(valid ? gr : 0) * DD) + c4;
            uint32_t dst = s_st + idx * 16;
            int sz = valid ? 16 : 0;          // sz=0 -> zero-fill, no read
            asm volatile("cp.async.cg.shared.global [%0], [%1], 16, %2;"
                         :: "r"(dst), "l"(g), "r"(sz));
        }
    }
    asm volatile("cp.async.commit_group;");
}

__global__ void __launch_bounds__(512, 1) k_big(const float* __restrict__ proxies) {
    extern __shared__ uint32_t smu[];
    uint32_t* As = smu;                        // 512 x 68
    uint32_t* Ps = smu + BB * 68;              // 64 x 68
    float* Stg = (float*)(smu + (BB + TC) * 68);  // 2 x 64x128 f32

    const int tid = threadIdx.x;
    const int w = tid >> 5, lane = tid & 31, gid = lane >> 2, tig = lane & 3;
    const int grp = lane >> 3, lr = lane & 7;
    const uint32_t s_as = s2u(As), s_ps = s2u(Ps), s_st = s2u(Stg);

    const int stride = gridDim.x;
    int t = blockIdx.x;

    // prologue: fill both staging buffers
    cp_tile(proxies, s_st, t, tid);
    {
        int t1 = t + stride;
        cp_tile(proxies, s_st + STGF * 4, (t1 < NT) ? t1 : -1, tid);
    }

    // stage Xs (bf16) into padded As while cp.async flies
    const uint32_t* Xg = (const uint32_t*)g_Xs16;
    for (int i = tid; i < BB * (DD / 2); i += 512)
        As[(i >> 6) * 68 + (i & 63)] = Xg[i];

    float rs[2][2];
    rs[0][0] = rs[0][1] = rs[1][0] = rs[1][1] = 0.f;

    // ldmatrix address pieces
    const uint32_t aRowBase = (uint32_t)(w * 32 + (grp & 1) * 8 + lr);
    const uint32_t aKadd = (uint32_t)((grp >> 1) * 4);
    const uint32_t bRowBase = (uint32_t)((grp >> 1) * 8 + lr);
    const uint32_t bKadd = (uint32_t)((grp & 1) * 4);

    // conv indexing: 8 threads per proxy row
    const int cRow = tid >> 3, cSub = tid & 7;

    // folded constants: exp(-relu(18-2acc)) = 2^min(2*log2e*acc - 18*log2e, 0)
    const float C2L = 2.8853900817779268f;     // 2*log2(e)
    const float SXL = 25.96851073600134f;      // 18*log2(e)

    int cur = 0;
    while (t < NT) {
        asm volatile("cp.async.wait_group 1;");
        __syncthreads();   // staging[cur] (tile t) visible to all

        // normalize staging -> bf16 Ps
        {
            const float4* Sg = (const float4*)(Stg + cur * STGF);
            float4 q0 = Sg[cRow * 32 + cSub * 4 + 0];
            float4 q1 = Sg[cRow * 32 + cSub * 4 + 1];
            float4 q2 = Sg[cRow * 32 + cSub * 4 + 2];
            float4 q3 = Sg[cRow * 32 + cSub * 4 + 3];
            float s = q0.x * q0.x + q0.y * q0.y + q0.z * q0.z + q0.w * q0.w
                    + q1.x * q1.x + q1.y * q1.y + q1.z * q1.z + q1.w * q1.w
                    + q2.x * q2.x + q2.y * q2.y + q2.z * q2.z + q2.w * q2.w
                    + q3.x * q3.x + q3.y * q3.y + q3.z * q3.z + q3.w * q3.w;
            s += __shfl_xor_sync(0xffffffffu, s, 4);
            s += __shfl_xor_sync(0xffffffffu, s, 2);
            s += __shfl_xor_sync(0xffffffffu, s, 1);
            float sc = (s > 0.f) ? 3.f * rsqrtf(s) : 0.f;
            uint4 o0, o1;
            o0.x = f2b2(q0.x * sc, q0.y * sc); o0.y = f2b2(q0.z * sc, q0.w * sc);
            o0.z = f2b2(q1.x * sc, q1.y * sc); o0.w = f2b2(q1.z * sc, q1.w * sc);
            o1.x = f2b2(q2.x * sc, q2.y * sc); o1.y = f2b2(q2.z * sc, q2.w * sc);
            o1.z = f2b2(q3.x * sc, q3.y * sc); o1.w = f2b2(q3.z * sc, q3.w * sc);
            uint4* dst = (uint4*)(Ps + cRow * 68 + cSub * 8);
            dst[0] = o0; dst[1] = o1;
        }
        __syncthreads();   // Ps ready; staging[cur] fully consumed

        // refill staging[cur] with tile t + 2*stride (overlaps mma)
        {
            int t2 = t + 2 * stride;
            cp_tile(proxies, s_st + cur * STGF * 4, (t2 < NT) ? t2 : -1, tid);
        }

        float acc[2][8][4];
#pragma unroll
        for (int mf = 0; mf < 2; mf++)
#pragma unroll
            for (int n = 0; n < 8; n++) {
                acc[mf][n][0] = 0.f; acc[mf][n][1] = 0.f;
                acc[mf][n][2] = 0.f; acc[mf][n][3] = 0.f;
            }

#pragma unroll
        for (int ks = 0; ks < 8; ks++) {
            uint32_t kb = ks * 8;
            uint32_t a[2][4];
#pragma unroll
            for (int mf = 0; mf < 2; mf++)
                ldsm4(s_as + ((aRowBase + mf * 16) * 68 + kb + aKadd) * 4, a[mf]);
            uint32_t bq[8][2];
#pragma unroll
            for (int np = 0; np < 4; np++) {
                uint32_t r4[4];
                ldsm4(s_ps + ((bRowBase + np * 16) * 68 + kb + bKadd) * 4, r4);
                bq[2 * np][0] = r4[0]; bq[2 * np][1] = r4[1];
                bq[2 * np + 1][0] = r4[2]; bq[2 * np + 1][1] = r4[3];
            }
#pragma unroll
            for (int mf = 0; mf < 2; mf++)
#pragma unroll
                for (int n = 0; n < 8; n++)
                    mma_bf16(acc[mf][n], a[mf][0], a[mf][1], a[mf][2], a[mf][3],
                             bq[n][0], bq[n][1]);
        }

        // epilogue: rs += 2^min(C2L*acc - SXL, 0)
#pragma unroll
        for (int mf = 0; mf < 2; mf++) {
#pragma unroll
            for (int n = 0; n < 8; n++) {
                float e0 = fminf(fmaf(C2L, acc[mf][n][0], -SXL), 0.f);
                float e1 = fminf(fmaf(C2L, acc[mf][n][1], -SXL), 0.f);
                float e2 = fminf(fmaf(C2L, acc[mf][n][2], -SXL), 0.f);
                float e3 = fminf(fmaf(C2L, acc[mf][n][3], -SXL), 0.f);
                rs[mf][0] += ex2f(e0) + ex2f(e1);
                rs[mf][1] += ex2f(e2) + ex2f(e3);
            }
        }

        cur ^= 1;
        t += stride;
    }

    // flush: quad-reduce over tig, one atomicAdd per row
#pragma unroll
    for (int mf = 0; mf < 2; mf++) {
#pragma unroll
        for (int h = 0; h < 2; h++) {
            float v = rs[mf][h];
            v += __shfl_xor_sync(0xffffffffu, v, 1);
            v += __shfl_xor_sync(0xffffffffu, v, 2);
            if (tig == 0)
                atomicAdd(&g_Z[w * 32 + mf * 16 + h * 8 + gid], v);
        }
    }
}

// ---------------------------------------------------------------------------
// K5: out = mean_b( Dt[b] + log(Z[b]) )
// ---------------------------------------------------------------------------
__global__ void k_final(float* __restrict__ out) {
    __shared__ float sw[16];
    int tid = threadIdx.x;
    float v = g_Dt[tid] + logf(g_Z[tid]);
#pragma unroll
    for (int o = 16; o; o >>= 1) v += __shfl_xor_sync(0xffffffffu, v, o);
    if ((tid & 31) == 0) sw[tid >> 5] = v;
    __syncthreads();
    if (tid < 32) {
        float u = (tid < 16) ? sw[tid] : 0.f;
#pragma unroll
        for (int o = 8; o; o >>= 1) u += __shfl_xor_sync(0xffffffffu, u, o);
        if (tid == 0) out[0] = u / (float)BB;
    }
}

// ---------------------------------------------------------------------------
// launch
// ---------------------------------------------------------------------------
extern "C" void kernel_launch(void* const* d_in, const int* in_sizes, int n_in,
                              void* d_out, int out_size) {
    const float* X = (const float*)d_in[0];
    const int* T32 = (const int*)d_in[2];
    const float* proxies = (const float*)d_in[3];
    float* out = (float*)d_out;

    int sms = 0;
    cudaDeviceGetAttribute(&sms, cudaDevAttrMultiProcessorCount, 0);
    if (sms <= 0) sms = 148;
    cudaFuncSetAttribute(k_big, cudaFuncAttributeMaxDynamicSharedMemorySize, SMEM_BIG);
    cudaFuncSetAttribute(k_att, cudaFuncAttributeMaxDynamicSharedMemorySize, SMEM_ATT);

    k_prep<<<BB, DD>>>(X, T32, proxies);
    dim3 ga(16, 16);
    k_att<<<ga, 256, SMEM_ATT>>>();
    k_xw<<<128, 256>>>();
    k_big<<<sms, 512, SMEM_BIG>>>(proxies);
    k_final<<<1, BB>>>(out);
}